// round 17
// baseline (speedup 1.0000x reference)
#include <cuda_runtime.h>
#include <math.h>

#define GRID_N   16
#define IN_DIM   64
#define OUT_DIM  64
#define BATCH    1024
#define NCOEF    19

#define BT 32                 // batch tile (warp lanes = b)
#define OB 4                  // o-columns per block
#define IB 16                 // i-columns per block
#define THREADS 128

#define CS_F     (OB * IB * NCOEF)          // 1216 floats coef tile [oo][il][19]
#define CS_Q4    76                         // f4 per (o, i-chunk) slice: 16*19/4
#define S4_Q4    (BT * 16)                  // 512 f4 result buffer
#define XS_Q4    (BT * 5)                   // 160 f4 x tile (own region now)
#define SMEM_BYTES (CS_F * 4 + (S4_Q4 + XS_Q4) * 16)   // 15616 B -> 12 CTAs/SM ok

__global__ __launch_bounds__(THREADS, 12)   // 1536 thr -> 42 reg cap -> 40 regs
void kan_kernel(const float* __restrict__ x,
                const float* __restrict__ coef,
                const float* __restrict__ grid,
                float* __restrict__ out) {
    extern __shared__ float sm[];
    float*  cs  = sm;                              // coef [oo][il][19]
    float4* S4  = (float4*)(sm + CS_F);            // results [b][16 swz cols]
    float4* xs4 = (float4*)(sm + CS_F) + S4_Q4;    // x tile [b][4] pitch 5

    const int tid  = threadIdx.x;
    const int bid  = blockIdx.x;
    const int b0   = (bid & 31) * BT;        // 32 batch tiles
    const int rest = bid >> 5;               // 0..63
    const int o0   = (rest >> 2) * OB;       // 16 o-chunks
    const int ih   = rest & 3;               // 4 i-chunks: global i = ih*16 + il
    const int lane = tid & 31;               // -> b
    const int warp = tid >> 5;               // -> one i-quad (il = warp*4+j)

    // ---- Stage coef tile (coalesced LDG.128 -> linear STS.128).
    #pragma unroll
    for (int t = tid; t < OB * CS_Q4; t += THREADS) {
        int oo  = t / CS_Q4;                 // const-div -> mul
        int rem = t - oo * CS_Q4;
        ((float4*)cs)[t] =
            ((const float4*)coef)[(size_t)(o0 + oo) * 304 + ih * CS_Q4 + rem];
    }
    // ---- Stage x tile: 64B-segment coalesced loads, pitch-5 rows.
    {
        int row = tid >> 2, col = tid & 3;
        xs4[row * 5 + col] =
            ((const float4*)x)[(size_t)(b0 + row) * 16 + ih * 4 + col];
    }
    const float g3    = grid[3];
    const float inv_h = 1.0f / (grid[4] - g3);
    const float k6    = 1.0f / 6.0f;
    __syncthreads();

    // This thread's x quad: pitch-5 read, bank walk lane*5 mod 8 -> conflict-free.
    const float4 xq = xs4[lane * 5 + warp];

    // ---- Compute: weights once per i (quad), reused across 4 o's.
    float4 racc[OB];
    #pragma unroll
    for (int j = 0; j < 4; j++) {
        const float xv = (j == 0) ? xq.x : (j == 1) ? xq.y : (j == 2) ? xq.z : xq.w;
        float t = (xv - g3) * inv_h;
        int i0 = __float2int_rd(t);
        i0 = min(GRID_N - 1, max(0, i0));
        const float u  = t - (float)i0;
        const float om = 1.0f - u;
        const float u2 = u * u;
        const float w0 = om * om * om * k6;
        const float w3 = u2 * u * k6;
        const float w1 = fmaf(u2, fmaf(0.5f, u, -1.0f), 2.0f / 3.0f);
        const float w2 = 1.0f - w0 - w1 - w3;
        const int base = (warp * 4 + j) * NCOEF + i0;

        #pragma unroll
        for (int oo = 0; oo < OB; oo++) {
            // lanes=b: addrs in a 19-word window -> bank-conflict-free scalar LDS.
            const float* c = cs + oo * (IB * NCOEF) + base;
            float r = fmaf(w3, c[3], fmaf(w2, c[2], fmaf(w1, c[1], w0 * c[0])));
            if      (j == 0) racc[oo].x = r;
            else if (j == 1) racc[oo].y = r;
            else if (j == 2) racc[oo].z = r;
            else             racc[oo].w = r;
        }
    }
    // S4 write: col = (oo*4 + warp) ^ (lane&15) -> minimum-phase STS.128.
    #pragma unroll
    for (int oo = 0; oo < OB; oo++)
        S4[lane * 16 + ((oo * 4 + warp) ^ (lane & 15))] = racc[oo];
    __syncthreads();

    // ---- Store: 512 f4, 4/thread; swizzle-inverted LDS.128, coalesced STG.128.
    #pragma unroll
    for (int k = 0; k < 4; k++) {
        int t   = tid + k * THREADS;
        int i4s = t & 3;
        int oo  = (t >> 2) & 3;
        int bb  = t >> 4;
        float4 v = S4[bb * 16 + ((oo * 4 + i4s) ^ (bb & 15))];
        reinterpret_cast<float4*>(out)[
            ((size_t)(b0 + bb) * OUT_DIM + (o0 + oo)) * (IN_DIM / 4) + ih * 4 + i4s] = v;
    }
}

extern "C" void kernel_launch(void* const* d_in, const int* in_sizes, int n_in,
                              void* d_out, int out_size) {
    const float* x    = (const float*)d_in[0];
    const float* coef = (const float*)d_in[1];
    const float* grid = (const float*)d_in[2];
    float* out        = (float*)d_out;

    cudaFuncSetAttribute(kan_kernel, cudaFuncAttributeMaxDynamicSharedMemorySize,
                         SMEM_BYTES);
    kan_kernel<<<(BATCH / BT) * (OUT_DIM / OB) * (IN_DIM / IB), THREADS, SMEM_BYTES>>>(
        x, coef, grid, out);
}